// round 1
// baseline (speedup 1.0000x reference)
#include <cuda_runtime.h>
#include <math.h>

#define BATCH 32
#define NCLS 3
#define HH 192
#define WW 640
#define HW (HH*WW)
#define NPL (BATCH*NCLS)
#define KTOP 50
#define NEG_INF -3.402823466e38f
#define PI_F 3.14159265358979f
#define DET_THR 0.25f

// -------- scratch (static device globals; no allocs allowed) --------
__device__ int   g_count[NPL];
__device__ float g_cval[NPL][HW];
__device__ int   g_cidx[NPL][HW];
__device__ float g_topv[NPL][KTOP];
__device__ int   g_topi[NPL][KTOP];

__constant__ float c_dimref[3][3] = {
    {3.88f, 1.63f, 1.53f},
    {0.84f, 1.76f, 0.66f},
    {1.78f, 1.52f, 1.78f}};

__global__ void k_zero() {
    int t = threadIdx.x;
    if (t < NPL) g_count[t] = 0;
}

__device__ __forceinline__ float max3(float a, float b, float c) {
    return fmaxf(a, fmaxf(b, c));
}

// -------- pass 1: fused 3x3 NMS + survivor compaction --------
// One thread = 4 consecutive pixels (float4). Separable column-max.
__global__ void k_nms(const float* __restrict__ heat) {
    int plane = blockIdx.y;
    int t = blockIdx.x * blockDim.x + threadIdx.x;   // 0..(HH*WW/4 - 1), exact grid
    int y  = t / (WW / 4);
    int xq = t - y * (WW / 4);
    int xb = xq << 2;

    const float* p  = heat + (size_t)plane * HW;
    const float* rm = p + (y - 1) * WW + xb;
    const float* rc = p + y * WW + xb;
    const float* rp = p + (y + 1) * WW + xb;

    bool hm = (y > 0), hp = (y < HH - 1), hl = (xb > 0), hr = (xb + 4 < WW);

    float4 qm = hm ? *(const float4*)rm : make_float4(NEG_INF, NEG_INF, NEG_INF, NEG_INF);
    float4 qc = *(const float4*)rc;
    float4 qp = hp ? *(const float4*)rp : make_float4(NEG_INF, NEG_INF, NEG_INF, NEG_INF);

    float lm = (hm && hl) ? rm[-1] : NEG_INF;
    float lc = hl ? rc[-1] : NEG_INF;
    float lp = (hp && hl) ? rp[-1] : NEG_INF;
    float em = (hm && hr) ? rm[4] : NEG_INF;
    float ec = hr ? rc[4] : NEG_INF;
    float ep = (hp && hr) ? rp[4] : NEG_INF;

    float cm0 = max3(lm, lc, lp);
    float cm1 = max3(qm.x, qc.x, qp.x);
    float cm2 = max3(qm.y, qc.y, qp.y);
    float cm3 = max3(qm.z, qc.z, qp.z);
    float cm4 = max3(qm.w, qc.w, qp.w);
    float cm5 = max3(em, ec, ep);

    float vv[4] = {qc.x, qc.y, qc.z, qc.w};
    float hx[4] = {max3(cm0, cm1, cm2), max3(cm1, cm2, cm3),
                   max3(cm2, cm3, cm4), max3(cm3, cm4, cm5)};

    int lane = threadIdx.x & 31;
#pragma unroll
    for (int i = 0; i < 4; i++) {
        bool s = (hx[i] == vv[i]);   // hmax (incl. self) == value  <=>  kept by NMS
        unsigned msk = __ballot_sync(0xffffffffu, s);
        if (s) {
            int leader = __ffs(msk) - 1;
            int base;
            if (lane == leader) base = atomicAdd(&g_count[plane], __popc(msk));
            base = __shfl_sync(msk, base, leader);
            int off = base + __popc(msk & ((1u << lane) - 1u));
            g_cval[plane][off] = vv[i];
            g_cidx[plane][off] = y * WW + xb + i;
        }
    }
}

// -------- pass 2: per-plane exact top-50 of survivor list --------
// 1024 threads/plane. Each thread keeps a register-sorted top-8 of its strided
// slice; 50 rounds of two-level argmax with (val desc, idx asc) tie order.
__global__ __launch_bounds__(1024) void k_planetop() {
    int plane = blockIdx.x;
    int tid = threadIdx.x;
    int n = g_count[plane];

    float v[8];
    int   ix[8];
#pragma unroll
    for (int k = 0; k < 8; k++) { v[k] = NEG_INF; ix[k] = 0x7fffffff; }

    for (int i = tid; i < n; i += 1024) {
        float val = g_cval[plane][i];
        int   id  = g_cidx[plane][i];
        if (val > v[7] || (val == v[7] && id < ix[7])) {
            v[7] = val; ix[7] = id;
#pragma unroll
            for (int k = 7; k > 0; k--) {
                bool better = (v[k] > v[k-1]) || (v[k] == v[k-1] && ix[k] < ix[k-1]);
                if (better) {
                    float tv = v[k]; v[k] = v[k-1]; v[k-1] = tv;
                    int ti = ix[k]; ix[k] = ix[k-1]; ix[k-1] = ti;
                }
            }
        }
    }

    __shared__ float swv[32];
    __shared__ int   swi[32];
    __shared__ int   swt[32];
    __shared__ float winv;
    __shared__ int   wini;
    __shared__ int   wint;

    int lane = tid & 31, wid = tid >> 5;

    for (int it = 0; it < KTOP; it++) {
        float bv = v[0]; int bi = ix[0]; int bt = tid;
#pragma unroll
        for (int off = 16; off; off >>= 1) {
            float ov = __shfl_down_sync(0xffffffffu, bv, off);
            int   oi = __shfl_down_sync(0xffffffffu, bi, off);
            int   ot = __shfl_down_sync(0xffffffffu, bt, off);
            if (ov > bv || (ov == bv && oi < bi)) { bv = ov; bi = oi; bt = ot; }
        }
        if (lane == 0) { swv[wid] = bv; swi[wid] = bi; swt[wid] = bt; }
        __syncthreads();
        if (wid == 0) {
            bv = swv[lane]; bi = swi[lane]; bt = swt[lane];
#pragma unroll
            for (int off = 16; off; off >>= 1) {
                float ov = __shfl_down_sync(0xffffffffu, bv, off);
                int   oi = __shfl_down_sync(0xffffffffu, bi, off);
                int   ot = __shfl_down_sync(0xffffffffu, bt, off);
                if (ov > bv || (ov == bv && oi < bi)) { bv = ov; bi = oi; bt = ot; }
            }
            if (lane == 0) { winv = bv; wini = bi; wint = bt; }
        }
        __syncthreads();
        if (tid == wint) {   // winner pops its head
#pragma unroll
            for (int k = 0; k < 7; k++) { v[k] = v[k+1]; ix[k] = ix[k+1]; }
            v[7] = NEG_INF; ix[7] = 0x7fffffff;
        }
        if (tid == 0) {
            float wv = winv; int wi = wini;
            if (wv < -1e30f) { wv = 0.0f; wi = 0; }  // <50 survivors: pad (below threshold anyway)
            g_topv[plane][it] = wv;
            g_topi[plane][it] = wi;
        }
        __syncthreads();
    }
}

// -------- pass 3: per-batch top-50 of 150 + full detection math --------
__device__ __forceinline__ void inv3(const float* M, float* R) {
    float a = M[0], b = M[1], c = M[2];
    float d = M[3], e = M[4], f = M[5];
    float g = M[6], h = M[7], i = M[8];
    float A = e * i - f * h;
    float Bm = -(d * i - f * g);
    float C = d * h - e * g;
    float det = a * A + b * Bm + c * C;
    float id = 1.0f / det;
    R[0] = A * id;             R[1] = -(b * i - c * h) * id;  R[2] = (b * f - c * e) * id;
    R[3] = Bm * id;            R[4] = (a * i - c * g) * id;   R[5] = -(a * f - c * d) * id;
    R[6] = C * id;             R[7] = -(a * h - b * g) * id;  R[8] = (a * e - b * d) * id;
}

__global__ void k_final(const float* __restrict__ reg,
                        const float* __restrict__ tmat,
                        const float* __restrict__ Kmat,
                        const float* __restrict__ img,
                        float* __restrict__ out) {
    int b = blockIdx.x;
    int tid = threadIdx.x;

    __shared__ float sv[150];
    __shared__ int   si[150];
    __shared__ float rv[KTOP];
    __shared__ int   ri[KTOP];
    __shared__ int   rc[KTOP];

    if (tid < 150) {
        int plane = b * NCLS + tid / KTOP;
        sv[tid] = g_topv[plane][tid % KTOP];
        si[tid] = g_topi[plane][tid % KTOP];
    }
    __syncthreads();

    if (tid < 150) {
        float mv = sv[tid];
        int rank = 0;
        for (int j = 0; j < 150; j++) {
            float o = sv[j];
            if (o > mv || (o == mv && j < tid)) rank++;
        }
        if (rank < KTOP) {
            rv[rank] = mv;
            ri[rank] = si[tid];
            rc[rank] = tid / KTOP;
        }
    }
    __syncthreads();

    if (tid >= KTOP) return;

    float score = rv[tid];
    float* o = out + ((size_t)b * KTOP + tid) * 14;

    if (!(score > DET_THR)) {
#pragma unroll
        for (int k = 0; k < 14; k++) o[k] = 0.0f;
        return;
    }

    int ind = ri[tid];
    int cls = rc[tid];
    float xs = (float)(ind % WW);
    float ys = (float)(ind / WW);

    float r8[8];
#pragma unroll
    for (int ch = 0; ch < 8; ch++)
        r8[ch] = reg[((size_t)b * 8 + ch) * HW + ind];

    float T[9], Ti[9], Kk[9], Ki[9];
#pragma unroll
    for (int k = 0; k < 9; k++) { T[k] = tmat[b * 9 + k]; Kk[k] = Kmat[b * 9 + k]; }
    inv3(T, Ti);
    inv3(Kk, Ki);

    float px = xs + r8[1];
    float py = ys + r8[2];
    float pix = Ti[0] * px + Ti[1] * py + Ti[2];
    float piy = Ti[3] * px + Ti[4] * py + Ti[5];
    float piz = Ti[6] * px + Ti[7] * py + Ti[8];

    float depth = r8[0] * 16.32f + 28.01f;
    float vx = pix * depth, vy = piy * depth, vz = piz * depth;
    float lx = Ki[0] * vx + Ki[1] * vy + Ki[2] * vz;
    float ly = Ki[3] * vx + Ki[4] * vy + Ki[5] * vz;
    float lz = Ki[6] * vx + Ki[7] * vy + Ki[8] * vz;

    float d0 = expf(r8[3]) * c_dimref[cls][0];
    float d1 = expf(r8[4]) * c_dimref[cls][1];
    float d2 = expf(r8[5]) * c_dimref[cls][2];
    ly += d1 * 0.5f;

    float rays = atanf(lx / (lz + 1e-7f));
    float al = atanf(r8[6] / (r8[7] + 1e-7f));
    al += (r8[7] >= 0.0f) ? -PI_F * 0.5f : PI_F * 0.5f;
    float roty = al + rays;
    roty = (roty > PI_F) ? roty - 2.0f * PI_F : ((roty < -PI_F) ? roty + 2.0f * PI_F : roty);
    al   = (al   > PI_F) ? al   - 2.0f * PI_F : ((al   < -PI_F) ? al   + 2.0f * PI_F : al);

    const float SX[8] = {-0.5f, 0.5f, 0.5f, 0.5f, 0.5f, -0.5f, -0.5f, -0.5f};
    const float SY[8] = {-1.0f, -1.0f, 0.0f, 0.0f, -1.0f, -1.0f, 0.0f, 0.0f};
    const float SZ[8] = {-0.5f, -0.5f, -0.5f, 0.5f, 0.5f, 0.5f, 0.5f, -0.5f};

    float cr = cosf(roty), sr = sinf(roty);
    float umin = 3.4e38f, umax = -3.4e38f, wmin = 3.4e38f, wmax = -3.4e38f;
#pragma unroll
    for (int j = 0; j < 8; j++) {
        float cx = d0 * SX[j], cy = d1 * SY[j], cz = d2 * SZ[j];
        float wx = cr * cx + sr * cz + lx;
        float wy = cy + ly;
        float wz = -sr * cx + cr * cz + lz;
        float qx = Kk[0] * wx + Kk[1] * wy + Kk[2] * wz;
        float qy = Kk[3] * wx + Kk[4] * wy + Kk[5] * wz;
        float qz = Kk[6] * wx + Kk[7] * wy + Kk[8] * wz;
        float u = qx / qz;
        float w = qy / qz;
        umin = fminf(umin, u); umax = fmaxf(umax, u);
        wmin = fminf(wmin, w); wmax = fmaxf(wmax, w);
    }

    float Wi = img[b * 2 + 0], Hi = img[b * 2 + 1];
    float xmin = fminf(fmaxf(umin, 0.0f), Wi);
    float ymin = fminf(fmaxf(wmin, 0.0f), Hi);
    float xmax = fminf(fmaxf(umax, 0.0f), Wi);
    float ymax = fminf(fmaxf(wmax, 0.0f), Hi);

    o[0]  = (float)cls;
    o[1]  = al;
    o[2]  = xmin;
    o[3]  = ymin;
    o[4]  = xmax;
    o[5]  = ymax;
    o[6]  = d1;   // dims rolled -1: (d1, d2, d0)
    o[7]  = d2;
    o[8]  = d0;
    o[9]  = lx;
    o[10] = ly;
    o[11] = lz;
    o[12] = roty;
    o[13] = score;
}

extern "C" void kernel_launch(void* const* d_in, const int* in_sizes, int n_in,
                              void* d_out, int out_size) {
    const float* heat = (const float*)d_in[0];
    const float* reg  = (const float*)d_in[1];
    const float* tm   = (const float*)d_in[2];
    const float* Km   = (const float*)d_in[3];
    const float* img  = (const float*)d_in[4];
    float* out = (float*)d_out;

    k_zero<<<1, 128>>>();
    dim3 g_nms((HH * (WW / 4)) / 256, NPL);   // 30720/256 = 120 exact
    k_nms<<<g_nms, 256>>>(heat);
    k_planetop<<<NPL, 1024>>>();
    k_final<<<BATCH, 160>>>(reg, tm, Km, img, out);
}

// round 2
// speedup vs baseline: 3.8828x; 3.8828x over previous
#include <cuda_runtime.h>
#include <math.h>

#define BATCH 32
#define NCLS 3
#define HH 192
#define WW 640
#define HW (HH*WW)
#define NPL (BATCH*NCLS)
#define KTOP 50
#define NEG_INF -3.402823466e38f
#define PI_F 3.14159265358979f
#define DET_THR 0.25f

typedef unsigned long long u64;
typedef unsigned int u32;

// -------- scratch (static device globals; zero-initialized at load) --------
__device__ int g_count[NPL];
__device__ u64 g_ckey[NPL][HW];          // packed (val_bits<<32 | ~idx)
__device__ u64 g_topk[NPL][KTOP];

__constant__ float c_dimref[3][3] = {
    {3.88f, 1.63f, 1.53f},
    {0.84f, 1.76f, 0.66f},
    {1.78f, 1.52f, 1.78f}};

__device__ __forceinline__ float max3(float a, float b, float c) {
    return fmaxf(a, fmaxf(b, c));
}
__device__ __forceinline__ u64 pack_key(float v, int idx) {
    return ((u64)__float_as_uint(v) << 32) | (u32)(~idx);
}

// -------- pass 1: fused 3x3 NMS + thresholded block-aggregated compaction ----
// One thread = 4 consecutive pixels (float4). Separable column-max.
// ONE global atomicAdd per block (was: per warp-ballot -> LTS serialization).
__global__ __launch_bounds__(256) void k_nms(const float* __restrict__ heat) {
    int plane = blockIdx.y;
    int t = blockIdx.x * blockDim.x + threadIdx.x;   // exact grid
    int y  = t / (WW / 4);
    int xq = t - y * (WW / 4);
    int xb = xq << 2;

    const float* p  = heat + (size_t)plane * HW;
    const float* rm = p + (y - 1) * WW + xb;
    const float* rc = p + y * WW + xb;
    const float* rp = p + (y + 1) * WW + xb;

    bool hm = (y > 0), hp = (y < HH - 1), hl = (xb > 0), hr = (xb + 4 < WW);

    float4 qm = hm ? *(const float4*)rm : make_float4(NEG_INF, NEG_INF, NEG_INF, NEG_INF);
    float4 qc = *(const float4*)rc;
    float4 qp = hp ? *(const float4*)rp : make_float4(NEG_INF, NEG_INF, NEG_INF, NEG_INF);

    float lm = (hm && hl) ? rm[-1] : NEG_INF;
    float lc = hl ? rc[-1] : NEG_INF;
    float lp = (hp && hl) ? rp[-1] : NEG_INF;
    float em = (hm && hr) ? rm[4] : NEG_INF;
    float ec = hr ? rc[4] : NEG_INF;
    float ep = (hp && hr) ? rp[4] : NEG_INF;

    float cm0 = max3(lm, lc, lp);
    float cm1 = max3(qm.x, qc.x, qp.x);
    float cm2 = max3(qm.y, qc.y, qp.y);
    float cm3 = max3(qm.z, qc.z, qp.z);
    float cm4 = max3(qm.w, qc.w, qp.w);
    float cm5 = max3(em, ec, ep);

    float vv[4] = {qc.x, qc.y, qc.z, qc.w};
    float hx[4] = {max3(cm0, cm1, cm2), max3(cm1, cm2, cm3),
                   max3(cm2, cm3, cm4), max3(cm3, cm4, cm5)};

    // local survivors (score>thr filter is exact: <=thr rows are zeroed in the
    // output and can never displace a >thr candidate in either top-k stage)
    u64 keys[4];
    int cnt = 0;
#pragma unroll
    for (int i = 0; i < 4; i++) {
        if (hx[i] == vv[i] && vv[i] > DET_THR) {
            keys[cnt++] = pack_key(vv[i], y * WW + xb + i);
        }
    }

    // block-wide compaction: warp scan + shared warp totals + 1 global atomic
    int lane = threadIdx.x & 31, wid = threadIdx.x >> 5;
    int x = cnt;
#pragma unroll
    for (int off = 1; off < 32; off <<= 1) {
        int yv = __shfl_up_sync(0xffffffffu, x, off);
        if (lane >= off) x += yv;
    }
    int warp_excl = x - cnt;

    __shared__ int wtot[8];
    __shared__ int gbase;
    if (lane == 31) wtot[wid] = x;
    __syncthreads();
    if (threadIdx.x == 0) {
        int s = 0;
#pragma unroll
        for (int w = 0; w < 8; w++) { int c = wtot[w]; wtot[w] = s; s += c; }
        gbase = (s > 0) ? atomicAdd(&g_count[plane], s) : 0;
    }
    __syncthreads();

    int base = gbase + wtot[wid] + warp_excl;
    for (int j = 0; j < cnt; j++)
        g_ckey[plane][base + j] = keys[j];
}

// -------- pass 2: per-plane exact top-50 over packed u64 keys --------
__global__ __launch_bounds__(1024) void k_planetop() {
    int plane = blockIdx.x;
    int tid = threadIdx.x;
    int n = g_count[plane];
    __syncthreads();                 // all read n before reset
    if (tid == 0) g_count[plane] = 0;  // leave zeroed for next graph replay

    u64 v[8];
#pragma unroll
    for (int k = 0; k < 8; k++) v[k] = 0ULL;   // valid keys are > 0 (val>0.25)

    for (int i = tid; i < n; i += 1024) {
        u64 key = g_ckey[plane][i];
        if (key > v[7]) {
            v[7] = key;
#pragma unroll
            for (int k = 7; k > 0; k--) {
                if (v[k] > v[k-1]) { u64 tv = v[k]; v[k] = v[k-1]; v[k-1] = tv; }
            }
        }
    }

    __shared__ u64 swk[32];
    __shared__ u64 wink;
    int lane = tid & 31, wid = tid >> 5;

    for (int it = 0; it < KTOP; it++) {
        u64 k = v[0];
#pragma unroll
        for (int off = 16; off; off >>= 1) {
            u64 ok = __shfl_down_sync(0xffffffffu, k, off);
            if (ok > k) k = ok;
        }
        if (lane == 0) swk[wid] = k;
        __syncthreads();
        if (wid == 0) {
            k = swk[lane];
#pragma unroll
            for (int off = 16; off; off >>= 1) {
                u64 ok = __shfl_down_sync(0xffffffffu, k, off);
                if (ok > k) k = ok;
            }
            if (lane == 0) wink = k;
        }
        __syncthreads();
        u64 w = wink;
        if (tid == 0) g_topk[plane][it] = w;     // w==0 => padding (score 0.0)
        if (v[0] == w && w != 0ULL) {            // winner pops (idx unique)
#pragma unroll
            for (int k2 = 0; k2 < 7; k2++) v[k2] = v[k2+1];
            v[7] = 0ULL;
        }
        __syncthreads();
    }
}

// -------- pass 3: per-batch top-50 of 150 + full detection math --------
__device__ __forceinline__ void inv3(const float* M, float* R) {
    float a = M[0], b = M[1], c = M[2];
    float d = M[3], e = M[4], f = M[5];
    float g = M[6], h = M[7], i = M[8];
    float A = e * i - f * h;
    float Bm = -(d * i - f * g);
    float C = d * h - e * g;
    float det = a * A + b * Bm + c * C;
    float id = 1.0f / det;
    R[0] = A * id;  R[1] = -(b * i - c * h) * id;  R[2] = (b * f - c * e) * id;
    R[3] = Bm * id; R[4] = (a * i - c * g) * id;   R[5] = -(a * f - c * d) * id;
    R[6] = C * id;  R[7] = -(a * h - b * g) * id;  R[8] = (a * e - b * d) * id;
}

__global__ __launch_bounds__(160) void k_final(const float* __restrict__ reg,
                        const float* __restrict__ tmat,
                        const float* __restrict__ Kmat,
                        const float* __restrict__ img,
                        float* __restrict__ out) {
    int b = blockIdx.x;
    int tid = threadIdx.x;

    __shared__ float sv[150];
    __shared__ int   si[150];
    __shared__ float sreg[150][8];
    __shared__ float rv[KTOP];
    __shared__ int   rc[KTOP];
    __shared__ int   rsrc[KTOP];

    int myind = 0;
    if (tid < 150) {
        u64 k = g_topk[b * NCLS + tid / KTOP][tid % KTOP];
        sv[tid] = __uint_as_float((u32)(k >> 32));
        int ind = (int)(~(u32)k);
        if ((unsigned)ind >= HW) ind = 0;        // padding entries: clamp (unused)
        si[tid] = ind;
        myind = ind;
        // prefetch 8 reg channels now; DRAM latency overlaps the rank loop
#pragma unroll
        for (int ch = 0; ch < 8; ch++)
            sreg[tid][ch] = reg[((size_t)b * 8 + ch) * HW + myind];
    }
    __syncthreads();

    if (tid < 150) {
        float mv = sv[tid];
        int rank = 0;
        for (int j = 0; j < 150; j++) {
            float o = sv[j];
            if (o > mv || (o == mv && j < tid)) rank++;
        }
        if (rank < KTOP) {
            rv[rank] = mv;
            rc[rank] = tid / KTOP;
            rsrc[rank] = tid;
        }
    }
    __syncthreads();

    if (tid >= KTOP) return;

    float score = rv[tid];
    float* o = out + ((size_t)b * KTOP + tid) * 14;

    if (!(score > DET_THR)) {
#pragma unroll
        for (int k = 0; k < 14; k++) o[k] = 0.0f;
        return;
    }

    int src = rsrc[tid];
    int ind = si[src];
    int cls = rc[tid];
    float xs = (float)(ind % WW);
    float ys = (float)(ind / WW);

    float r8[8];
#pragma unroll
    for (int ch = 0; ch < 8; ch++) r8[ch] = sreg[src][ch];

    float T[9], Ti[9], Kk[9], Ki[9];
#pragma unroll
    for (int k = 0; k < 9; k++) { T[k] = tmat[b * 9 + k]; Kk[k] = Kmat[b * 9 + k]; }
    inv3(T, Ti);
    inv3(Kk, Ki);

    float px = xs + r8[1];
    float py = ys + r8[2];
    float pix = Ti[0] * px + Ti[1] * py + Ti[2];
    float piy = Ti[3] * px + Ti[4] * py + Ti[5];
    float piz = Ti[6] * px + Ti[7] * py + Ti[8];

    float depth = r8[0] * 16.32f + 28.01f;
    float vx = pix * depth, vy = piy * depth, vz = piz * depth;
    float lx = Ki[0] * vx + Ki[1] * vy + Ki[2] * vz;
    float ly = Ki[3] * vx + Ki[4] * vy + Ki[5] * vz;
    float lz = Ki[6] * vx + Ki[7] * vy + Ki[8] * vz;

    float d0 = expf(r8[3]) * c_dimref[cls][0];
    float d1 = expf(r8[4]) * c_dimref[cls][1];
    float d2 = expf(r8[5]) * c_dimref[cls][2];
    ly += d1 * 0.5f;

    float rays = atanf(lx / (lz + 1e-7f));
    float al = atanf(r8[6] / (r8[7] + 1e-7f));
    al += (r8[7] >= 0.0f) ? -PI_F * 0.5f : PI_F * 0.5f;
    float roty = al + rays;
    roty = (roty > PI_F) ? roty - 2.0f * PI_F : ((roty < -PI_F) ? roty + 2.0f * PI_F : roty);
    al   = (al   > PI_F) ? al   - 2.0f * PI_F : ((al   < -PI_F) ? al   + 2.0f * PI_F : al);

    const float SX[8] = {-0.5f, 0.5f, 0.5f, 0.5f, 0.5f, -0.5f, -0.5f, -0.5f};
    const float SY[8] = {-1.0f, -1.0f, 0.0f, 0.0f, -1.0f, -1.0f, 0.0f, 0.0f};
    const float SZ[8] = {-0.5f, -0.5f, -0.5f, 0.5f, 0.5f, 0.5f, 0.5f, -0.5f};

    float cr = cosf(roty), sr = sinf(roty);
    float umin = 3.4e38f, umax = -3.4e38f, wmin = 3.4e38f, wmax = -3.4e38f;
#pragma unroll
    for (int j = 0; j < 8; j++) {
        float cx = d0 * SX[j], cy = d1 * SY[j], cz = d2 * SZ[j];
        float wx = cr * cx + sr * cz + lx;
        float wy = cy + ly;
        float wz = -sr * cx + cr * cz + lz;
        float qx = Kk[0] * wx + Kk[1] * wy + Kk[2] * wz;
        float qy = Kk[3] * wx + Kk[4] * wy + Kk[5] * wz;
        float qz = Kk[6] * wx + Kk[7] * wy + Kk[8] * wz;
        float u = qx / qz;
        float w = qy / qz;
        umin = fminf(umin, u); umax = fmaxf(umax, u);
        wmin = fminf(wmin, w); wmax = fmaxf(wmax, w);
    }

    float Wi = img[b * 2 + 0], Hi = img[b * 2 + 1];
    float xmin = fminf(fmaxf(umin, 0.0f), Wi);
    float ymin = fminf(fmaxf(wmin, 0.0f), Hi);
    float xmax = fminf(fmaxf(umax, 0.0f), Wi);
    float ymax = fminf(fmaxf(wmax, 0.0f), Hi);

    o[0]  = (float)cls;
    o[1]  = al;
    o[2]  = xmin;
    o[3]  = ymin;
    o[4]  = xmax;
    o[5]  = ymax;
    o[6]  = d1;   // dims rolled -1: (d1, d2, d0)
    o[7]  = d2;
    o[8]  = d0;
    o[9]  = lx;
    o[10] = ly;
    o[11] = lz;
    o[12] = roty;
    o[13] = score;
}

extern "C" void kernel_launch(void* const* d_in, const int* in_sizes, int n_in,
                              void* d_out, int out_size) {
    const float* heat = (const float*)d_in[0];
    const float* reg  = (const float*)d_in[1];
    const float* tm   = (const float*)d_in[2];
    const float* Km   = (const float*)d_in[3];
    const float* img  = (const float*)d_in[4];
    float* out = (float*)d_out;

    dim3 g_nms((HH * (WW / 4)) / 256, NPL);   // 120 x 96
    k_nms<<<g_nms, 256>>>(heat);
    k_planetop<<<NPL, 1024>>>();
    k_final<<<BATCH, 160>>>(reg, tm, Km, img, out);
}

// round 3
// speedup vs baseline: 7.2868x; 1.8767x over previous
#include <cuda_runtime.h>
#include <math.h>

#define BATCH 32
#define NCLS 3
#define HH 192
#define WW 640
#define HW (HH*WW)
#define NPL (BATCH*NCLS)
#define KTOP 50
#define NEG_INF -3.402823466e38f
#define PI_F 3.14159265358979f
#define DET_THR 0.25f
#define RROWS 8
#define WCAP 256
#define CCAP 1024

typedef unsigned long long u64;
typedef unsigned int u32;

// -------- scratch (static device globals; zero-initialized at load) --------
__device__ int g_count[NPL];
__device__ u64 g_ckey[NPL][HW];          // packed (val_bits<<32 | ~idx)
__device__ u64 g_topk[NPL][KTOP];

__constant__ float c_dimref[3][3] = {
    {3.88f, 1.63f, 1.53f},
    {0.84f, 1.76f, 0.66f},
    {1.78f, 1.52f, 1.78f}};

__device__ __forceinline__ float max3(float a, float b, float c) {
    return fmaxf(a, fmaxf(b, c));
}
__device__ __forceinline__ u64 pack_key(float v, int idx) {
    return ((u64)__float_as_uint(v) << 32) | (u32)(~idx);
}

// -------- pass 1: rolling-window 3x3 NMS, each pixel loaded once --------
// Block = 160 threads = 5 warps spanning the full 640-px row width.
// Each thread processes RROWS=8 output rows at fixed xb, keeping a 3-row
// float4 window in registers. Horizontal neighbors via shfl; edge columns
// via 1 scalar load/row on lanes 0/31 only. Zero atomics in the hot loop.
__global__ __launch_bounds__(160) void k_nms(const float* __restrict__ heat) {
    int plane = blockIdx.y;
    int warp = threadIdx.x >> 5;     // 0..4
    int lane = threadIdx.x & 31;
    int xb = warp * 128 + lane * 4;
    int y0 = blockIdx.x * RROWS;
    const float* p = heat + (size_t)plane * HW;
    bool hasL = (xb > 0);
    bool hasR = (xb + 4 < WW);

    float4 a, b;
    float la0, la1, ra0, ra1;
    if (y0 > 0) a = *(const float4*)(p + (y0 - 1) * WW + xb);
    else        a = make_float4(NEG_INF, NEG_INF, NEG_INF, NEG_INF);
    b = *(const float4*)(p + y0 * WW + xb);
    la0 = (lane == 0 && hasL && y0 > 0) ? p[(y0 - 1) * WW + xb - 1] : NEG_INF;
    la1 = (lane == 0 && hasL)           ? p[y0 * WW + xb - 1]       : NEG_INF;
    ra0 = (lane == 31 && hasR && y0 > 0) ? p[(y0 - 1) * WW + xb + 4] : NEG_INF;
    ra1 = (lane == 31 && hasR)           ? p[y0 * WW + xb + 4]       : NEG_INF;

    __shared__ int wcnt[5];
    __shared__ int spref[5];
    __shared__ int sgbase;
    __shared__ u64 sbuf[5][WCAP];

    int wrun = 0;   // replicated per-warp running count (all lanes agree)

#pragma unroll
    for (int r = 0; r < RROWS; r++) {
        int y = y0 + r;
        int yn = y + 1;
        float4 c;
        float la2 = NEG_INF, ra2 = NEG_INF;
        if (yn < HH) {
            c = *(const float4*)(p + yn * WW + xb);
            if (lane == 0 && hasL)  la2 = p[yn * WW + xb - 1];
            if (lane == 31 && hasR) ra2 = p[yn * WW + xb + 4];
        } else {
            c = make_float4(NEG_INF, NEG_INF, NEG_INF, NEG_INF);
        }

        float4 cm;
        cm.x = max3(a.x, b.x, c.x);
        cm.y = max3(a.y, b.y, c.y);
        cm.z = max3(a.z, b.z, c.z);
        cm.w = max3(a.w, b.w, c.w);
        float lmx = max3(la0, la1, la2);
        float rmx = max3(ra0, ra1, ra2);

        float left = __shfl_up_sync(0xffffffffu, cm.w, 1);
        if (lane == 0) left = lmx;
        float right = __shfl_down_sync(0xffffffffu, cm.x, 1);
        if (lane == 31) right = rmx;

        float h0 = max3(left, cm.x, cm.y);
        float h1 = max3(cm.x, cm.y, cm.z);
        float h2 = max3(cm.y, cm.z, cm.w);
        float h3 = max3(cm.z, cm.w, right);

        // survivors: hmax(3x3 incl self)==val, score>thr (exact: <=thr rows
        // are zeroed in the output and can't displace >thr candidates)
        u64 keys[4];
        int cnt = 0;
        int bi = y * WW + xb;
        if (h0 == b.x && b.x > DET_THR) keys[cnt++] = pack_key(b.x, bi);
        if (h1 == b.y && b.y > DET_THR) keys[cnt++] = pack_key(b.y, bi + 1);
        if (h2 == b.z && b.z > DET_THR) keys[cnt++] = pack_key(b.z, bi + 2);
        if (h3 == b.w && b.w > DET_THR) keys[cnt++] = pack_key(b.w, bi + 3);

        // warp exclusive scan of cnt (no atomics)
        int x = cnt;
#pragma unroll
        for (int off = 1; off < 32; off <<= 1) {
            int yv = __shfl_up_sync(0xffffffffu, x, off);
            if (lane >= off) x += yv;
        }
        int excl = x - cnt;
        int tot = __shfl_sync(0xffffffffu, x, 31);

        for (int j = 0; j < cnt; j++) {
            int pos = wrun + excl + j;
            if (pos < WCAP) sbuf[warp][pos] = keys[j];
        }
        wrun += tot;

        a = b; b = c;
        la0 = la1; la1 = la2;
        ra0 = ra1; ra1 = ra2;
    }

    if (wrun > WCAP) wrun = WCAP;
    if (lane == 0) wcnt[warp] = wrun;
    __syncthreads();
    if (threadIdx.x == 0) {
        int s = 0;
#pragma unroll
        for (int w = 0; w < 5; w++) { spref[w] = s; s += wcnt[w]; }
        sgbase = (s > 0) ? atomicAdd(&g_count[plane], s) : 0;
    }
    __syncthreads();

    int myc = wcnt[warp];
    u64* dst = &g_ckey[plane][sgbase + spref[warp]];
    for (int j = lane; j < myc; j += 32)
        dst[j] = sbuf[warp][j];
}

// -------- pass 2: per-plane exact top-50 via histogram threshold --------
__global__ __launch_bounds__(1024) void k_planetop() {
    int plane = blockIdx.x;
    int tid = threadIdx.x;

    __shared__ int hist[1024];
    __shared__ int sn, sB, sccount;
    __shared__ u64 cand[CCAP];

    if (tid == 0) {
        sn = g_count[plane];
        g_count[plane] = 0;   // reset for next graph replay
        sccount = 0;
    }
    hist[tid] = 0;
    __syncthreads();

    int n = sn;
    const u64* ck = g_ckey[plane];

    // pass A: histogram of value bits (monotonic buckets over (0.25, 1.0+])
    for (int i = tid; i < n; i += 1024) {
        u32 vb = (u32)(ck[i] >> 32);
        int bkt = (int)((vb - 0x3e800000u) >> 14);
        if (bkt > 1023) bkt = 1023;
        atomicAdd(&hist[bkt], 1);
    }
    __syncthreads();

    if (tid == 0) {
        int cum = 0, bsel = 0;
        for (int bkt = 1023; bkt >= 0; bkt--) {
            cum += hist[bkt];
            if (cum >= KTOP) { bsel = bkt; break; }
        }
        sB = bsel;
    }
    __syncthreads();

    u64 kmin = ((u64)(0x3e800000u + ((u32)sB << 14))) << 32;

    // pass B: compact candidates >= bucket threshold (~50-70 expected)
    for (int i = tid; i < n; i += 1024) {
        u64 k = ck[i];
        if (k >= kmin) {
            int pos = atomicAdd(&sccount, 1);
            if (pos < CCAP) cand[pos] = k;
        }
    }
    if (tid < KTOP) g_topk[plane][tid] = 0;   // padding when <50 candidates
    __syncthreads();

    int m = min(sccount, CCAP);
    if (tid < m) {
        u64 k = cand[tid];
        int rank = 0;
        for (int j = 0; j < m; j++) rank += (cand[j] > k);
        if (rank < KTOP) g_topk[plane][rank] = k;
    }
}

// -------- pass 3: per-batch top-50 of 150 + full detection math --------
__device__ __forceinline__ void inv3(const float* M, float* R) {
    float a = M[0], b = M[1], c = M[2];
    float d = M[3], e = M[4], f = M[5];
    float g = M[6], h = M[7], i = M[8];
    float A = e * i - f * h;
    float Bm = -(d * i - f * g);
    float C = d * h - e * g;
    float det = a * A + b * Bm + c * C;
    float id = 1.0f / det;
    R[0] = A * id;  R[1] = -(b * i - c * h) * id;  R[2] = (b * f - c * e) * id;
    R[3] = Bm * id; R[4] = (a * i - c * g) * id;   R[5] = -(a * f - c * d) * id;
    R[6] = C * id;  R[7] = -(a * h - b * g) * id;  R[8] = (a * e - b * d) * id;
}

__global__ __launch_bounds__(160) void k_final(const float* __restrict__ reg,
                        const float* __restrict__ tmat,
                        const float* __restrict__ Kmat,
                        const float* __restrict__ img,
                        float* __restrict__ out) {
    int b = blockIdx.x;
    int tid = threadIdx.x;

    __shared__ float sv[150];

    float score = 0.0f;
    int ind = 0;
    float r8[8];

    if (tid < 150) {
        u64 k = g_topk[b * NCLS + tid / KTOP][tid % KTOP];
        score = __uint_as_float((u32)(k >> 32));
        ind = (int)(~(u32)k);
        if ((unsigned)ind >= HW) ind = 0;
        sv[tid] = score;
        // gather 8 reg channels (MLP=8; overlaps everything below)
#pragma unroll
        for (int ch = 0; ch < 8; ch++)
            r8[ch] = reg[((size_t)b * 8 + ch) * HW + ind];
    }
    __syncthreads();

    if (tid >= 150) return;

    // rank among 150 (stable: value desc, position asc) — exact lax.top_k order
    float mv = sv[tid];
    int rank = 0;
    for (int j = 0; j < 150; j++) {
        float o = sv[j];
        if (o > mv || (o == mv && j < tid)) rank++;
    }
    if (rank >= KTOP) return;

    float* o = out + ((size_t)b * KTOP + rank) * 14;

    if (!(score > DET_THR)) {
#pragma unroll
        for (int k = 0; k < 14; k++) o[k] = 0.0f;
        return;
    }

    int cls = tid / KTOP;
    float xs = (float)(ind % WW);
    float ys = (float)(ind / WW);

    float T[9], Ti[9], Kk[9], Ki[9];
#pragma unroll
    for (int k = 0; k < 9; k++) { T[k] = tmat[b * 9 + k]; Kk[k] = Kmat[b * 9 + k]; }
    inv3(T, Ti);
    inv3(Kk, Ki);

    float px = xs + r8[1];
    float py = ys + r8[2];
    float pix = Ti[0] * px + Ti[1] * py + Ti[2];
    float piy = Ti[3] * px + Ti[4] * py + Ti[5];
    float piz = Ti[6] * px + Ti[7] * py + Ti[8];

    float depth = r8[0] * 16.32f + 28.01f;
    float vx = pix * depth, vy = piy * depth, vz = piz * depth;
    float lx = Ki[0] * vx + Ki[1] * vy + Ki[2] * vz;
    float ly = Ki[3] * vx + Ki[4] * vy + Ki[5] * vz;
    float lz = Ki[6] * vx + Ki[7] * vy + Ki[8] * vz;

    float d0 = __expf(r8[3]) * c_dimref[cls][0];
    float d1 = __expf(r8[4]) * c_dimref[cls][1];
    float d2 = __expf(r8[5]) * c_dimref[cls][2];
    ly += d1 * 0.5f;

    float rays = atanf(__fdividef(lx, lz + 1e-7f));
    float al = atanf(__fdividef(r8[6], r8[7] + 1e-7f));
    al += (r8[7] >= 0.0f) ? -PI_F * 0.5f : PI_F * 0.5f;
    float roty = al + rays;
    roty = (roty > PI_F) ? roty - 2.0f * PI_F : ((roty < -PI_F) ? roty + 2.0f * PI_F : roty);
    al   = (al   > PI_F) ? al   - 2.0f * PI_F : ((al   < -PI_F) ? al   + 2.0f * PI_F : al);

    const float SX[8] = {-0.5f, 0.5f, 0.5f, 0.5f, 0.5f, -0.5f, -0.5f, -0.5f};
    const float SY[8] = {-1.0f, -1.0f, 0.0f, 0.0f, -1.0f, -1.0f, 0.0f, 0.0f};
    const float SZ[8] = {-0.5f, -0.5f, -0.5f, 0.5f, 0.5f, 0.5f, 0.5f, -0.5f};

    float sr, cr;
    __sincosf(roty, &sr, &cr);
    float umin = 3.4e38f, umax = -3.4e38f, wmin = 3.4e38f, wmax = -3.4e38f;
#pragma unroll
    for (int j = 0; j < 8; j++) {
        float cx = d0 * SX[j], cy = d1 * SY[j], cz = d2 * SZ[j];
        float wx = cr * cx + sr * cz + lx;
        float wy = cy + ly;
        float wz = -sr * cx + cr * cz + lz;
        float qx = Kk[0] * wx + Kk[1] * wy + Kk[2] * wz;
        float qy = Kk[3] * wx + Kk[4] * wy + Kk[5] * wz;
        float qz = Kk[6] * wx + Kk[7] * wy + Kk[8] * wz;
        float rq = __fdividef(1.0f, qz);
        float u = qx * rq;
        float w = qy * rq;
        umin = fminf(umin, u); umax = fmaxf(umax, u);
        wmin = fminf(wmin, w); wmax = fmaxf(wmax, w);
    }

    float Wi = img[b * 2 + 0], Hi = img[b * 2 + 1];
    float xmin = fminf(fmaxf(umin, 0.0f), Wi);
    float ymin = fminf(fmaxf(wmin, 0.0f), Hi);
    float xmax = fminf(fmaxf(umax, 0.0f), Wi);
    float ymax = fminf(fmaxf(wmax, 0.0f), Hi);

    o[0]  = (float)cls;
    o[1]  = al;
    o[2]  = xmin;
    o[3]  = ymin;
    o[4]  = xmax;
    o[5]  = ymax;
    o[6]  = d1;   // dims rolled -1: (d1, d2, d0)
    o[7]  = d2;
    o[8]  = d0;
    o[9]  = lx;
    o[10] = ly;
    o[11] = lz;
    o[12] = roty;
    o[13] = score;
}

extern "C" void kernel_launch(void* const* d_in, const int* in_sizes, int n_in,
                              void* d_out, int out_size) {
    const float* heat = (const float*)d_in[0];
    const float* reg  = (const float*)d_in[1];
    const float* tm   = (const float*)d_in[2];
    const float* Km   = (const float*)d_in[3];
    const float* img  = (const float*)d_in[4];
    float* out = (float*)d_out;

    dim3 g_nms(HH / RROWS, NPL);   // 24 x 96
    k_nms<<<g_nms, 160>>>(heat);
    k_planetop<<<NPL, 1024>>>();
    k_final<<<BATCH, 160>>>(reg, tm, Km, img, out);
}